// round 10
// baseline (speedup 1.0000x reference)
#include <cuda_runtime.h>

#define NC 62
#define HW_BITS 18
#define HW (1 << HW_BITS)
#define NP (8 * HW)                      // 2,097,152 pixels
#define NTHREADS 128
#define NBLOCKS 8192
#define TILE_PX 32
#define NTILES (NP / TILE_PX)            // 65536
#define TILES_PER_CTA (NTILES / NBLOCKS) // 8
#define STAGES 2
#define RS 36                            // row stride: 32 px + 4 pad (bank-conflict-free)
#define TILE_FLOATS (NC * RS)            // 2232
#define TGT_OFF TILE_FLOATS
#define STAGE_FLOATS (TILE_FLOATS + TILE_PX)   // 2264
#define SMEM_BYTES (STAGES * STAGE_FLOATS * 4) // 18112 -> 9 CTAs/SM
#define IGN 255
#define SMOOTH 1e-6f
#define PAD 32
#define OWNER_MASK 0x000F000Fu           // lanes 0-3 and 16-19 (h<4 per q-group)
#define CHUNKS (NC * 8 + 8)              // 504 cp.async 16B chunks per tile

__device__ float g_acc[NC * PAD];
__device__ float g_inter[NC * PAD];
__device__ float g_tgt[NC * PAD];
__device__ unsigned int g_count;

// Stage fill: 62 rows x 8 16B-chunks (pred, 128B fully-coalesced per row)
// + 8 chunks (32 targets) = 504 cp.async ops
__device__ __forceinline__ void fill_stage(float* sm, const float* pred,
                                           const int* target, int tile, int tid) {
    int n = tile >> (HW_BITS - 5);                       // tile / 8192
    size_t hw0 = (size_t)(tile & ((1 << (HW_BITS - 5)) - 1)) << 5;
    unsigned sbase = (unsigned)__cvta_generic_to_shared(sm);
#pragma unroll
    for (int k = 0; k < 4; k++) {
        int idx = tid + k * NTHREADS;                    // 0..511
        if (idx < NC * 8) {
            int c = idx >> 3, ch = idx & 7;
            const float* src =
                pred + (((size_t)(n * NC + c)) << HW_BITS) + hw0 + ch * 4;
            unsigned dst = sbase + (unsigned)((c * RS + ch * 4) * 4);
            asm volatile("cp.async.cg.shared.global [%0], [%1], 16;"
                         :: "r"(dst), "l"(src));
        } else if (idx < CHUNKS) {
            int ch = idx - NC * 8;
            const int* src = target + (size_t)tile * TILE_PX + ch * 4;
            unsigned dst = sbase + (unsigned)((TGT_OFF + ch * 4) * 4);
            asm volatile("cp.async.cg.shared.global [%0], [%1], 16;"
                         :: "r"(dst), "l"(src));
        }
    }
}

__global__ __launch_bounds__(NTHREADS, 9) void dice_kernel(
    const float* __restrict__ pred, const int* __restrict__ target,
    float* __restrict__ out) {
    extern __shared__ float smem[];
    __shared__ float s_acc[NC];
    __shared__ float s_inter[NC];
    __shared__ float s_tgt[NC];
    __shared__ bool s_last;

    int tid = threadIdx.x;
    int lane = tid & 31;
    int w = tid >> 5;        // warp 0..3, owns pixels [w*8, w*8+8) of each tile
    int h = lane & 15;       // channel chunk: c = j*16 + h (j<4)
    int q = lane >> 4;       // pixel quad 0..1 within the warp's 8 px

    if (tid < NC) {
        s_acc[tid] = 0.0f;
        s_inter[tid] = 0.0f;
        s_tgt[tid] = 0.0f;
    }

    // Prologue: prefetch stages 0..1
#pragma unroll
    for (int s = 0; s < STAGES; s++) {
        fill_stage(smem + s * STAGE_FLOATS, pred, target,
                   blockIdx.x + s * NBLOCKS, tid);
        asm volatile("cp.async.commit_group;");
    }

    float acc[4];
#pragma unroll
    for (int j = 0; j < 4; j++) acc[j] = 0.0f;

#pragma unroll 1
    for (int i = 0; i < TILES_PER_CTA; i++) {
        asm volatile("cp.async.wait_group 1;");
        __syncthreads();   // stage (i%2) resident for all 4 warps

        float* st = smem + (i % STAGES) * STAGE_FLOATS;
        const int* tg = (const int*)(st + TGT_OFF);

        int pxb = w * 8 + q * 4;   // this lane's quad base within the tile
        int4 t4 = *(const int4*)(tg + pxb);  // broadcast within 8-lane phase

        // Phase A: 4 LDS.128 per lane, conflict-free (bank = 4h + const)
        float4 v[4];
#pragma unroll
        for (int j = 0; j < 4; j++) {
            int c = j * 16 + h;
            v[j] = (c < NC) ? *(const float4*)(st + c * RS + pxb)
                            : make_float4(0.f, 0.f, 0.f, 0.f);
        }

        // Phase B: exp in place + per-pixel partial Z
        float zx = 0.f, zy = 0.f, zz = 0.f, zw = 0.f;
#pragma unroll
        for (int j = 0; j < 4; j++) {
            bool cv = (j * 16 + h < NC);
            float ex = cv ? __expf(v[j].x) : 0.f;
            float ey = cv ? __expf(v[j].y) : 0.f;
            float ez = cv ? __expf(v[j].z) : 0.f;
            float ew = cv ? __expf(v[j].w) : 0.f;
            v[j].x = ex; v[j].y = ey; v[j].z = ez; v[j].w = ew;
            zx += ex; zy += ey; zz += ez; zw += ew;
        }
        // combine Z across the 16 h-lanes of this quad (4 independent chains)
        zx += __shfl_xor_sync(0xffffffffu, zx, 1);
        zy += __shfl_xor_sync(0xffffffffu, zy, 1);
        zz += __shfl_xor_sync(0xffffffffu, zz, 1);
        zw += __shfl_xor_sync(0xffffffffu, zw, 1);
        zx += __shfl_xor_sync(0xffffffffu, zx, 2);
        zy += __shfl_xor_sync(0xffffffffu, zy, 2);
        zz += __shfl_xor_sync(0xffffffffu, zz, 2);
        zw += __shfl_xor_sync(0xffffffffu, zw, 2);
        zx += __shfl_xor_sync(0xffffffffu, zx, 4);
        zy += __shfl_xor_sync(0xffffffffu, zy, 4);
        zz += __shfl_xor_sync(0xffffffffu, zz, 4);
        zw += __shfl_xor_sync(0xffffffffu, zw, 4);
        zx += __shfl_xor_sync(0xffffffffu, zx, 8);
        zy += __shfl_xor_sync(0xffffffffu, zy, 8);
        zz += __shfl_xor_sync(0xffffffffu, zz, 8);
        zw += __shfl_xor_sync(0xffffffffu, zw, 8);

        float sx = (t4.x != IGN) ? __fdividef(1.f, zx) : 0.f;  // invZ * validf
        float sy = (t4.y != IGN) ? __fdividef(1.f, zy) : 0.f;
        float sz = (t4.z != IGN) ? __fdividef(1.f, zz) : 0.f;
        float sw = (t4.w != IGN) ? __fdividef(1.f, zw) : 0.f;

        // Phase C: per-class register accumulation
#pragma unroll
        for (int j = 0; j < 4; j++) {
            acc[j] = fmaf(v[j].x, sx,
                     fmaf(v[j].y, sy,
                     fmaf(v[j].z, sz,
                     fmaf(v[j].w, sw, acc[j]))));
        }

        // Phase D: lanes with h<4 own pixel pxb+h. Gather softmax[target]
        // straight from smem + shared atomics.
        if (h < 4) {
            int tmine = (h == 0) ? t4.x : (h == 1) ? t4.y : (h == 2) ? t4.z : t4.w;
            float smine = (h == 0) ? sx : (h == 1) ? sy : (h == 2) ? sz : sw;
            bool valid = (tmine != IGN);
            int tc = valid ? tmine : 0;
            float xt = st[tc * RS + pxb + h];
            atomicAdd(&s_inter[tc], __expf(xt) * smine);  // 0 if invalid

            unsigned m = __match_any_sync(OWNER_MASK, tc);
            unsigned vb = __ballot_sync(OWNER_MASK, valid);
            if (lane == (int)(__ffs(m) - 1)) {
                int cnt = __popc(m & vb);
                if (cnt) atomicAdd(&s_tgt[tc], (float)cnt);
            }
        }

        __syncthreads();   // all warps done with stage before refill
        if (i + STAGES < TILES_PER_CTA)
            fill_stage(smem + (i % STAGES) * STAGE_FLOATS, pred, target,
                       blockIdx.x + (i + STAGES) * NBLOCKS, tid);
        asm volatile("cp.async.commit_group;");  // keeps group count uniform
    }

    // Reduce acc across the 2 q-groups (xor 16), then to shared
#pragma unroll
    for (int j = 0; j < 4; j++) {
        float va = acc[j];
        va += __shfl_xor_sync(0xffffffffu, va, 16);
        if (lane < 16) {
            int c = j * 16 + lane;
            if (c < NC) atomicAdd(&s_acc[c], va);
        }
    }
    __syncthreads();

    // One global atomic per class per block (padded -> spread L2 slices)
    if (tid < NC) {
        atomicAdd(&g_acc[tid * PAD], s_acc[tid]);
        atomicAdd(&g_inter[tid * PAD], s_inter[tid]);
        atomicAdd(&g_tgt[tid * PAD], s_tgt[tid]);
    }
    __threadfence();
    __syncthreads();
    if (tid == 0) {
        unsigned prev = atomicAdd(&g_count, 1u);
        s_last = (prev == NBLOCKS - 1);
    }
    __syncthreads();
    if (!s_last) return;

    // ---- last block: finalize ----
    float dice = 0.0f, has = 0.0f;
    if (tid < NC) {
        float ps = atomicAdd(&g_acc[tid * PAD], 0.0f);
        float iv = atomicAdd(&g_inter[tid * PAD], 0.0f);
        float tg = atomicAdd(&g_tgt[tid * PAD], 0.0f);
        float un = ps + tg;
        if (un > 0.0f) {
            has = 1.0f;
            dice = (2.0f * iv + SMOOTH) / (un + SMOOTH);
        }
    }
    __shared__ float sd[4], sh[4];
#pragma unroll
    for (int o = 16; o > 0; o >>= 1) {
        dice += __shfl_xor_sync(0xffffffffu, dice, o);
        has += __shfl_xor_sync(0xffffffffu, has, o);
    }
    if (lane == 0) {
        sd[tid >> 5] = dice;
        sh[tid >> 5] = has;
    }
    __syncthreads();
    if (tid == 0) {
        float ds = 0.0f, hs = 0.0f;
#pragma unroll
        for (int ww = 0; ww < NTHREADS / 32; ww++) {
            ds += sd[ww];
            hs += sh[ww];
        }
        float mean = (hs > 0.0f) ? (ds / fmaxf(hs, 1.0f)) : 1.0f;
        out[0] = 1.0f - mean;
    }
    __syncthreads();
    // reset globals so every graph replay starts clean
    if (tid < NC) {
        g_acc[tid * PAD] = 0.0f;
        g_inter[tid * PAD] = 0.0f;
        g_tgt[tid * PAD] = 0.0f;
    }
    if (tid == 0) g_count = 0;
}

extern "C" void kernel_launch(void* const* d_in, const int* in_sizes, int n_in,
                              void* d_out, int out_size) {
    const float* pred = (const float*)d_in[0];
    const int* target = (const int*)d_in[1];
    float* out = (float*)d_out;
    cudaFuncSetAttribute(dice_kernel, cudaFuncAttributeMaxDynamicSharedMemorySize,
                         SMEM_BYTES);
    dice_kernel<<<NBLOCKS, NTHREADS, SMEM_BYTES>>>(pred, target, out);
}

// round 11
// speedup vs baseline: 1.0047x; 1.0047x over previous
#include <cuda_runtime.h>

#define NC 62
#define HW_BITS 18
#define HW (1 << HW_BITS)
#define NP (8 * HW)                      // 2,097,152 pixels
#define NTHREADS 128
#define NBLOCKS 8192
#define TILE_PX 32
#define NTILES (NP / TILE_PX)            // 65536
#define TILES_PER_CTA (NTILES / NBLOCKS) // 8
#define STAGES 2
#define RS 36                            // row stride: 32 px + 4 pad (bank-conflict-free)
#define TILE_FLOATS (NC * RS)            // 2232
#define TGT_OFF TILE_FLOATS
#define STAGE_FLOATS (TILE_FLOATS + TILE_PX)   // 2264
#define SMEM_BYTES (STAGES * STAGE_FLOATS * 4) // 18112 -> 9 CTAs/SM
#define IGN 255
#define SMOOTH 1e-6f
#define PAD 32
#define OWNER_MASK 0x000F000Fu           // lanes 0-3 and 16-19 (h<4 per q-group)
#define CHUNKS (NC * 8 + 8)              // 504 cp.async 16B chunks per tile

__device__ float g_acc[NC * PAD];
__device__ float g_inter[NC * PAD];
__device__ float g_tgt[NC * PAD];
__device__ unsigned int g_count;

// Stage fill: 62 rows x 8 16B-chunks (pred, 128B fully-coalesced per row)
// + 8 chunks (32 targets) = 504 cp.async ops
__device__ __forceinline__ void fill_stage(float* sm, const float* pred,
                                           const int* target, int tile, int tid) {
    int n = tile >> (HW_BITS - 5);                       // tile / 8192
    size_t hw0 = (size_t)(tile & ((1 << (HW_BITS - 5)) - 1)) << 5;
    unsigned sbase = (unsigned)__cvta_generic_to_shared(sm);
#pragma unroll
    for (int k = 0; k < 4; k++) {
        int idx = tid + k * NTHREADS;                    // 0..511
        if (idx < NC * 8) {
            int c = idx >> 3, ch = idx & 7;
            const float* src =
                pred + (((size_t)(n * NC + c)) << HW_BITS) + hw0 + ch * 4;
            unsigned dst = sbase + (unsigned)((c * RS + ch * 4) * 4);
            asm volatile("cp.async.cg.shared.global [%0], [%1], 16;"
                         :: "r"(dst), "l"(src));
        } else if (idx < CHUNKS) {
            int ch = idx - NC * 8;
            const int* src = target + (size_t)tile * TILE_PX + ch * 4;
            unsigned dst = sbase + (unsigned)((TGT_OFF + ch * 4) * 4);
            asm volatile("cp.async.cg.shared.global [%0], [%1], 16;"
                         :: "r"(dst), "l"(src));
        }
    }
}

__global__ __launch_bounds__(NTHREADS, 9) void dice_kernel(
    const float* __restrict__ pred, const int* __restrict__ target,
    float* __restrict__ out) {
    extern __shared__ float smem[];
    __shared__ float s_acc[NC];
    __shared__ float s_inter[NC];
    __shared__ float s_tgt[NC];
    __shared__ bool s_last;

    int tid = threadIdx.x;
    int lane = tid & 31;
    int w = tid >> 5;        // warp 0..3, owns pixels [w*8, w*8+8) of each tile
    int h = lane & 15;       // channel chunk: c = j*16 + h (j<4)
    int q = lane >> 4;       // pixel quad 0..1 within the warp's 8 px

    if (tid < NC) {
        s_acc[tid] = 0.0f;
        s_inter[tid] = 0.0f;
        s_tgt[tid] = 0.0f;
    }

    // Prologue: prefetch stages 0..1
#pragma unroll
    for (int s = 0; s < STAGES; s++) {
        fill_stage(smem + s * STAGE_FLOATS, pred, target,
                   blockIdx.x + s * NBLOCKS, tid);
        asm volatile("cp.async.commit_group;");
    }

    float acc[4];
#pragma unroll
    for (int j = 0; j < 4; j++) acc[j] = 0.0f;

#pragma unroll 1
    for (int i = 0; i < TILES_PER_CTA; i++) {
        asm volatile("cp.async.wait_group 1;");
        __syncthreads();   // stage (i%2) resident for all 4 warps

        float* st = smem + (i % STAGES) * STAGE_FLOATS;
        const int* tg = (const int*)(st + TGT_OFF);

        int pxb = w * 8 + q * 4;   // this lane's quad base within the tile
        int4 t4 = *(const int4*)(tg + pxb);  // broadcast within 8-lane phase

        // Phase A: 4 LDS.128 per lane, conflict-free (bank = 4h + const)
        float4 v[4];
#pragma unroll
        for (int j = 0; j < 4; j++) {
            int c = j * 16 + h;
            v[j] = (c < NC) ? *(const float4*)(st + c * RS + pxb)
                            : make_float4(0.f, 0.f, 0.f, 0.f);
        }

        // Phase B: exp in place + per-pixel partial Z
        float zx = 0.f, zy = 0.f, zz = 0.f, zw = 0.f;
#pragma unroll
        for (int j = 0; j < 4; j++) {
            bool cv = (j * 16 + h < NC);
            float ex = cv ? __expf(v[j].x) : 0.f;
            float ey = cv ? __expf(v[j].y) : 0.f;
            float ez = cv ? __expf(v[j].z) : 0.f;
            float ew = cv ? __expf(v[j].w) : 0.f;
            v[j].x = ex; v[j].y = ey; v[j].z = ez; v[j].w = ew;
            zx += ex; zy += ey; zz += ez; zw += ew;
        }
        // combine Z across the 16 h-lanes of this quad (4 independent chains)
        zx += __shfl_xor_sync(0xffffffffu, zx, 1);
        zy += __shfl_xor_sync(0xffffffffu, zy, 1);
        zz += __shfl_xor_sync(0xffffffffu, zz, 1);
        zw += __shfl_xor_sync(0xffffffffu, zw, 1);
        zx += __shfl_xor_sync(0xffffffffu, zx, 2);
        zy += __shfl_xor_sync(0xffffffffu, zy, 2);
        zz += __shfl_xor_sync(0xffffffffu, zz, 2);
        zw += __shfl_xor_sync(0xffffffffu, zw, 2);
        zx += __shfl_xor_sync(0xffffffffu, zx, 4);
        zy += __shfl_xor_sync(0xffffffffu, zy, 4);
        zz += __shfl_xor_sync(0xffffffffu, zz, 4);
        zw += __shfl_xor_sync(0xffffffffu, zw, 4);
        zx += __shfl_xor_sync(0xffffffffu, zx, 8);
        zy += __shfl_xor_sync(0xffffffffu, zy, 8);
        zz += __shfl_xor_sync(0xffffffffu, zz, 8);
        zw += __shfl_xor_sync(0xffffffffu, zw, 8);

        float sx = (t4.x != IGN) ? __fdividef(1.f, zx) : 0.f;  // invZ * validf
        float sy = (t4.y != IGN) ? __fdividef(1.f, zy) : 0.f;
        float sz = (t4.z != IGN) ? __fdividef(1.f, zz) : 0.f;
        float sw = (t4.w != IGN) ? __fdividef(1.f, zw) : 0.f;

        // Phase C: per-class register accumulation
#pragma unroll
        for (int j = 0; j < 4; j++) {
            acc[j] = fmaf(v[j].x, sx,
                     fmaf(v[j].y, sy,
                     fmaf(v[j].z, sz,
                     fmaf(v[j].w, sw, acc[j]))));
        }

        // Phase D: lanes with h<4 own pixel pxb+h. Gather softmax[target]
        // straight from smem + shared atomics.
        if (h < 4) {
            int tmine = (h == 0) ? t4.x : (h == 1) ? t4.y : (h == 2) ? t4.z : t4.w;
            float smine = (h == 0) ? sx : (h == 1) ? sy : (h == 2) ? sz : sw;
            bool valid = (tmine != IGN);
            int tc = valid ? tmine : 0;
            float xt = st[tc * RS + pxb + h];
            atomicAdd(&s_inter[tc], __expf(xt) * smine);  // 0 if invalid

            unsigned m = __match_any_sync(OWNER_MASK, tc);
            unsigned vb = __ballot_sync(OWNER_MASK, valid);
            if (lane == (int)(__ffs(m) - 1)) {
                int cnt = __popc(m & vb);
                if (cnt) atomicAdd(&s_tgt[tc], (float)cnt);
            }
        }

        __syncthreads();   // all warps done with stage before refill
        if (i + STAGES < TILES_PER_CTA)
            fill_stage(smem + (i % STAGES) * STAGE_FLOATS, pred, target,
                       blockIdx.x + (i + STAGES) * NBLOCKS, tid);
        asm volatile("cp.async.commit_group;");  // keeps group count uniform
    }

    // Reduce acc across the 2 q-groups (xor 16), then to shared
#pragma unroll
    for (int j = 0; j < 4; j++) {
        float va = acc[j];
        va += __shfl_xor_sync(0xffffffffu, va, 16);
        if (lane < 16) {
            int c = j * 16 + lane;
            if (c < NC) atomicAdd(&s_acc[c], va);
        }
    }
    __syncthreads();

    // One global atomic per class per block (padded -> spread L2 slices)
    if (tid < NC) {
        atomicAdd(&g_acc[tid * PAD], s_acc[tid]);
        atomicAdd(&g_inter[tid * PAD], s_inter[tid]);
        atomicAdd(&g_tgt[tid * PAD], s_tgt[tid]);
    }
    __threadfence();
    __syncthreads();
    if (tid == 0) {
        unsigned prev = atomicAdd(&g_count, 1u);
        s_last = (prev == NBLOCKS - 1);
    }
    __syncthreads();
    if (!s_last) return;

    // ---- last block: finalize ----
    float dice = 0.0f, has = 0.0f;
    if (tid < NC) {
        float ps = atomicAdd(&g_acc[tid * PAD], 0.0f);
        float iv = atomicAdd(&g_inter[tid * PAD], 0.0f);
        float tg = atomicAdd(&g_tgt[tid * PAD], 0.0f);
        float un = ps + tg;
        if (un > 0.0f) {
            has = 1.0f;
            dice = (2.0f * iv + SMOOTH) / (un + SMOOTH);
        }
    }
    __shared__ float sd[4], sh[4];
#pragma unroll
    for (int o = 16; o > 0; o >>= 1) {
        dice += __shfl_xor_sync(0xffffffffu, dice, o);
        has += __shfl_xor_sync(0xffffffffu, has, o);
    }
    if (lane == 0) {
        sd[tid >> 5] = dice;
        sh[tid >> 5] = has;
    }
    __syncthreads();
    if (tid == 0) {
        float ds = 0.0f, hs = 0.0f;
#pragma unroll
        for (int ww = 0; ww < NTHREADS / 32; ww++) {
            ds += sd[ww];
            hs += sh[ww];
        }
        float mean = (hs > 0.0f) ? (ds / fmaxf(hs, 1.0f)) : 1.0f;
        out[0] = 1.0f - mean;
    }
    __syncthreads();
    // reset globals so every graph replay starts clean
    if (tid < NC) {
        g_acc[tid * PAD] = 0.0f;
        g_inter[tid * PAD] = 0.0f;
        g_tgt[tid * PAD] = 0.0f;
    }
    if (tid == 0) g_count = 0;
}

extern "C" void kernel_launch(void* const* d_in, const int* in_sizes, int n_in,
                              void* d_out, int out_size) {
    const float* pred = (const float*)d_in[0];
    const int* target = (const int*)d_in[1];
    float* out = (float*)d_out;
    cudaFuncSetAttribute(dice_kernel, cudaFuncAttributeMaxDynamicSharedMemorySize,
                         SMEM_BYTES);
    dice_kernel<<<NBLOCKS, NTHREADS, SMEM_BYTES>>>(pred, target, out);
}